// round 14
// baseline (speedup 1.0000x reference)
#include <cuda_runtime.h>
#include <cuda_fp16.h>
#include <cstdint>
#include <cstddef>

#define M_DIM   16
#define K_DIM   4096
#define N_DIM   11008
#define NGROUPS 32
#define KINT    2048              // int32 per qweight row (1 byte payload each)

#define THREADS  256              // 8 warps x 32 cols
#define NT       43               // 43*256 = 11008
#define CTA_COLS 256
#define KSPLIT   8
#define KSEG     512
#define SEG_INT  256
#define NCH      16               // chunks per CTA
#define CH_INT   16               // ints per row per chunk (64 B)
#define NBUF     4
#define QROW_W   20               // padded words per row (80 B) -> conflict-free LDS
#define QBUF_SZ  (256 * QROW_W * 4)   // 20480 B
#define AS_H     520              // padded fp16 per A row (512+8)

#define SM_A    0                 // 16*520*2 = 16640 B
#define SM_Q    16640
#define SM_TOT  (16640 + NBUF * QBUF_SZ)   // 98560 B -> 2 CTAs/SM

__device__ float g_scratch[(size_t)KSPLIT * N_DIM * M_DIM];   // [k][n][m]
__device__ int   g_cnt[NT];

extern __shared__ __align__(1024) unsigned char smem_dyn[];

__device__ __forceinline__ uint32_t s2u(const void* p) {
    uint32_t a;
    asm("{ .reg .u64 t; cvta.to.shared.u64 t, %1; cvt.u32.u64 %0, t; }" : "=r"(a) : "l"(p));
    return a;
}
__device__ __forceinline__ void cp16(uint32_t d, const void* s) {
    asm volatile("cp.async.cg.shared.global [%0], [%1], 16;" :: "r"(d), "l"(s));
}
__device__ __forceinline__ void cp_commit() {
    asm volatile("cp.async.commit_group;" ::: "memory");
}
template<int N> __device__ __forceinline__ void cp_wait() {
    asm volatile("cp.async.wait_group %0;" :: "n"(N) : "memory");
}
__device__ __forceinline__ uint32_t h2bits(__half2 h) {
    return *reinterpret_cast<uint32_t*>(&h);
}
// packed byte q -> fp16x2 scaled weights, single-rounding (matches ref fp16 W for z=0)
__device__ __forceinline__ uint32_t dq(uint32_t q, uint32_t s2, uint32_t c2) {
    uint32_t w = 0x4C004C00u | ((q << 6) & 0x000003C0u) | ((q << 18) & 0x03C00000u);
    uint32_t r;
    asm("fma.rn.f16x2 %0, %1, %2, %3;" : "=r"(r) : "r"(w), "r"(s2), "r"(c2));
    return r;
}
#define MMA(C, A0, A1, A2, A3, B0, B1)                                         \
    asm volatile(                                                              \
        "mma.sync.aligned.m16n8k16.row.col.f32.f16.f16.f32 "                   \
        "{%0,%1,%2,%3}, {%4,%5,%6,%7}, {%8,%9}, {%0,%1,%2,%3};"                \
        : "+f"(C[0]), "+f"(C[1]), "+f"(C[2]), "+f"(C[3])                       \
        : "r"(A0), "r"(A1), "r"(A2), "r"(A3), "r"(B0), "r"(B1))

// Per-warp staging: warp w stages ONLY rows w*32..w*32+31 (2 KB payload/chunk)
// into an 80B-strided row layout; its own cp.async group -> no barriers.
__device__ __forceinline__ void stage_warp(const int* qw, int tile, int kidx,
                                           int ch, uint32_t buf, int warp, int lane) {
    const int rl = lane >> 2;         // 0..7
    const int u  = lane & 3;          // 16B unit within 64B row chunk
    #pragma unroll
    for (int i = 0; i < 4; i++) {
        int row = warp * 32 + i * 8 + rl;
        const int* src = qw + (size_t)(tile * CTA_COLS + row) * KINT
                       + kidx * SEG_INT + ch * CH_INT + u * 4;
        uint32_t dst = buf + (row * QROW_W + u * 4) * 4;
        cp16(dst, src);
    }
    cp_commit();
}

__global__ void __launch_bounds__(THREADS)
gptq_hmma(const float* __restrict__ A, const int* __restrict__ qw,
          const float* __restrict__ scales, const float* __restrict__ zeros,
          const float* __restrict__ bias, float* __restrict__ out) {
    __shared__ int s_ticket;

    const int t    = threadIdx.x;
    const int warp = t >> 5, lane = t & 31;
    const int tile = blockIdx.x;
    const int kidx = blockIdx.y;

    __half* As = (__half*)(smem_dyn + SM_A);
    uint32_t qb[NBUF];
    #pragma unroll
    for (int b = 0; b < NBUF; b++) qb[b] = s2u(smem_dyn + SM_Q + b * QBUF_SZ);

    // --- Kick off chunks 0..3 (per-warp groups) ---
    #pragma unroll
    for (int c0 = 0; c0 < NBUF; c0++)
        stage_warp(qw, tile, kidx, c0, qb[c0], warp, lane);

    // --- Stage A fp16 [16 m][512 k] (pad 520), whole CTA ---
    #pragma unroll
    for (int i = 0; i < 16; i++) {
        int idx = t + i * THREADS;            // 4096 float2
        int m   = idx >> 8;
        int kp  = idx & 255;
        float2 v = *(const float2*)(A + (size_t)m * K_DIM + kidx * KSEG + 2 * kp);
        *(__half2*)&As[m * AS_H + 2 * kp] = __floats2half2_rn(v.x, v.y);
    }
    __syncthreads();                          // A visible to all warps (only barrier)

    const int nb   = tile * CTA_COLS + warp * 32;
    const int colq = lane >> 2;               // 0..7
    const int kq   = lane & 3;

    size_t soff[4];
    int rbase[4];
    #pragma unroll
    for (int j = 0; j < 4; j++) {
        soff[j]  = (size_t)(nb + j * 8 + colq) * NGROUPS + kidx * 4;
        rbase[j] = (warp * 32 + j * 8 + colq) * QROW_W;
    }

    float scn[4], zzn[4];
    #pragma unroll
    for (int j = 0; j < 4; j++) { scn[j] = scales[soff[j]]; zzn[j] = zeros[soff[j]]; }

    float c[4][4];
    #pragma unroll
    for (int j = 0; j < 4; j++)
        #pragma unroll
        for (int p = 0; p < 4; p++) c[j][p] = 0.0f;

    uint32_t s2[4], c2[4];
    const uint32_t abase = s2u(As) + ((lane & 15) * AS_H + (lane >> 4) * 8) * 2;

    for (int ch = 0; ch < NCH; ch++) {
        // per-warp wait: chunk ch's group done, up to 3 deeper groups in flight
        if      (ch < NCH - 3) cp_wait<3>();
        else if (ch == NCH - 3) cp_wait<2>();
        else if (ch == NCH - 2) cp_wait<1>();
        else                    cp_wait<0>();

        if ((ch & 3) == 0) {                  // new quant group (4 chunks = 128 k)
            #pragma unroll
            for (int j = 0; j < 4; j++) {
                s2[j] = h2bits(__float2half2_rn(scn[j]));
                c2[j] = h2bits(__float2half2_rn(-(16.0f + zzn[j]) * scn[j]));
            }
            int g = ch >> 2;
            if (g < 3) {
                #pragma unroll
                for (int j = 0; j < 4; j++) {
                    scn[j] = scales[soff[j] + g + 1];
                    zzn[j] = zeros [soff[j] + g + 1];
                }
            }
        }

        const uint32_t* qwords =
            (const uint32_t*)(smem_dyn + SM_Q + (ch & (NBUF - 1)) * QBUF_SZ);
        #pragma unroll
        for (int ls = 0; ls < 2; ls++) {      // 2 k16-steps per chunk
            const int s = ch * 2 + ls;
            uint32_t a0, a1, a2, a3;
            asm volatile("ldmatrix.sync.aligned.m8n8.x4.shared.b16 {%0,%1,%2,%3}, [%4];"
                         : "=r"(a0), "=r"(a1), "=r"(a2), "=r"(a3)
                         : "r"(abase + s * 32));
            const int w0 = 8 * ls + kq;
            const int w1 = 8 * ls + 4 + kq;
            uint32_t q0[4], q1[4];
            #pragma unroll
            for (int j = 0; j < 4; j++) {
                q0[j] = qwords[rbase[j] + w0];
                q1[j] = qwords[rbase[j] + w1];
            }
            #pragma unroll
            for (int j = 0; j < 4; j++) {
                uint32_t b0 = dq(q0[j], s2[j], c2[j]);
                uint32_t b1 = dq(q1[j], s2[j], c2[j]);
                MMA(c[j], a0, a1, a2, a3, b0, b1);
            }
        }

        // refill the buffer this warp just finished (own rows only; no barrier)
        if (ch + NBUF < NCH)
            stage_warp(qw, tile, kidx, ch + NBUF, qb[ch & (NBUF - 1)], warp, lane);
    }

    // --- Store fp32 partials [kidx][n][m] ---
    #pragma unroll
    for (int j = 0; j < 4; j++) {
        int n0 = nb + j * 8 + 2 * kq;         // D cols = 2*(lane&3), +1
        int m0 = colq;                        // D rows = lane>>2, +8
        float* base = g_scratch + ((size_t)kidx * N_DIM + n0) * M_DIM;
        base[m0]              = c[j][0];
        base[M_DIM + m0]      = c[j][1];
        base[m0 + 8]          = c[j][2];
        base[M_DIM + m0 + 8]  = c[j][3];
    }

    // --- Ticket: last CTA of this tile reduces (deterministic k order) ---
    __threadfence();
    __syncthreads();
    if (t == 0) s_ticket = atomicAdd(&g_cnt[tile], 1);
    __syncthreads();
    if (s_ticket == KSPLIT - 1) {
        if (t == 0) g_cnt[tile] = 0;          // reset for next graph replay
        __threadfence();                       // acquire all partials
        int n = tile * CTA_COLS + t;
        float4 a0 = make_float4(0.f, 0.f, 0.f, 0.f), a1 = a0, a2 = a0, a3 = a0;
        #pragma unroll
        for (int kk = 0; kk < KSPLIT; kk++) {
            const float4* p = (const float4*)(g_scratch + ((size_t)kk * N_DIM + n) * M_DIM);
            float4 v0 = p[0], v1 = p[1], v2 = p[2], v3 = p[3];
            a0.x += v0.x; a0.y += v0.y; a0.z += v0.z; a0.w += v0.w;
            a1.x += v1.x; a1.y += v1.y; a1.z += v1.z; a1.w += v1.w;
            a2.x += v2.x; a2.y += v2.y; a2.z += v2.z; a2.w += v2.w;
            a3.x += v3.x; a3.y += v3.y; a3.z += v3.z; a3.w += v3.w;
        }
        float bv = bias[n];
        float r[16] = {a0.x, a0.y, a0.z, a0.w, a1.x, a1.y, a1.z, a1.w,
                       a2.x, a2.y, a2.z, a2.w, a3.x, a3.y, a3.z, a3.w};
        #pragma unroll
        for (int m = 0; m < 16; m++)
            out[(size_t)m * N_DIM + n] = r[m] + bv;
    }
}

extern "C" void kernel_launch(void* const* d_in, const int* in_sizes, int n_in,
                              void* d_out, int out_size) {
    const float* A      = (const float*)d_in[0];
    const int*   qwv    = (const int*)  d_in[1];
    const float* scales = (const float*)d_in[2];
    const float* zeros  = (const float*)d_in[3];
    const float* bias   = (const float*)d_in[4];
    float* out = (float*)d_out;

    cudaFuncSetAttribute(gptq_hmma, cudaFuncAttributeMaxDynamicSharedMemorySize, SM_TOT);
    gptq_hmma<<<dim3(NT, KSPLIT), THREADS, SM_TOT>>>(A, qwv, scales, zeros, bias, out);
}

// round 15
// speedup vs baseline: 1.2482x; 1.2482x over previous
#include <cuda_runtime.h>
#include <cuda_fp16.h>
#include <cstdint>
#include <cstddef>

#define M_DIM   16
#define K_DIM   4096
#define N_DIM   11008
#define NGROUPS 32
#define KINT    2048              // int32 per qweight row (1 byte payload each)

#define THREADS  256              // 8 warps x 32 cols
#define NT       43               // 43*256 = 11008
#define CTA_COLS 256
#define KSPLIT   8
#define KSEG     512
#define SEG_INT  256
#define NCH      8                // chunks per CTA
#define CH_INT   32               // ints per row per chunk (128 B)
#define AS_H     520              // padded fp16 per A row (512+8)

// dynamic smem: A tile + 2 qweight chunk buffers (rows are warp-private)
#define SM_A   0                  // 16*520*2 = 16640 B
#define SM_Q0  16640              // 256 rows * 128 B = 32768 B
#define SM_Q1  (16640 + 32768)
#define SM_TOT (16640 + 2 * 32768)   // 82176 B -> 2 CTAs/SM

__device__ float g_scratch[(size_t)KSPLIT * N_DIM * M_DIM];   // [k][n][m]
__device__ int   g_cnt[NT];

extern __shared__ __align__(1024) unsigned char smem_dyn[];

__device__ __forceinline__ uint32_t s2u(const void* p) {
    uint32_t a;
    asm("{ .reg .u64 t; cvta.to.shared.u64 t, %1; cvt.u32.u64 %0, t; }" : "=r"(a) : "l"(p));
    return a;
}
__device__ __forceinline__ void cp16(uint32_t d, const void* s) {
    asm volatile("cp.async.cg.shared.global [%0], [%1], 16;" :: "r"(d), "l"(s));
}
__device__ __forceinline__ void cp_commit() {
    asm volatile("cp.async.commit_group;" ::: "memory");
}
template<int N> __device__ __forceinline__ void cp_wait() {
    asm volatile("cp.async.wait_group %0;" :: "n"(N) : "memory");
}
__device__ __forceinline__ uint32_t h2bits(__half2 h) {
    return *reinterpret_cast<uint32_t*>(&h);
}
// packed byte q -> fp16x2 scaled weights, single-rounding (matches ref fp16 W for z=0)
__device__ __forceinline__ uint32_t dq(uint32_t q, uint32_t s2, uint32_t c2) {
    uint32_t w = 0x4C004C00u | ((q << 6) & 0x000003C0u) | ((q << 18) & 0x03C00000u);
    uint32_t r;
    asm("fma.rn.f16x2 %0, %1, %2, %3;" : "=r"(r) : "r"(w), "r"(s2), "r"(c2));
    return r;
}
#define MMA(C, A0, A1, A2, A3, B0, B1)                                         \
    asm volatile(                                                              \
        "mma.sync.aligned.m16n8k16.row.col.f32.f16.f16.f32 "                   \
        "{%0,%1,%2,%3}, {%4,%5,%6,%7}, {%8,%9}, {%0,%1,%2,%3};"                \
        : "+f"(C[0]), "+f"(C[1]), "+f"(C[2]), "+f"(C[3])                       \
        : "r"(A0), "r"(A1), "r"(A2), "r"(A3), "r"(B0), "r"(B1))

// Per-warp staging of the warp's OWN 32 rows (4 KB payload), 128 B per row,
// same swizzle as the R11 kernel; one cp.async group per warp per chunk.
__device__ __forceinline__ void stage_warp(const int* qw, int tile, int kidx,
                                           int ch, uint32_t buf, int warp, int lane) {
    const int rl  = lane >> 3;        // 0..3
    const int seg = lane & 7;         // 16B segment within 128B row chunk
    #pragma unroll
    for (int i = 0; i < 8; i++) {
        int row = warp * 32 + i * 4 + rl;
        const int* src = qw + (size_t)(tile * CTA_COLS + row) * KINT
                       + kidx * SEG_INT + ch * CH_INT + seg * 4;
        uint32_t dst = buf + row * 128 + ((seg ^ (row & 7)) << 4);
        cp16(dst, src);
    }
    cp_commit();
}

__global__ void __launch_bounds__(THREADS)
gptq_hmma(const float* __restrict__ A, const int* __restrict__ qw,
          const float* __restrict__ scales, const float* __restrict__ zeros,
          const float* __restrict__ bias, float* __restrict__ out) {
    __shared__ int s_ticket;

    const int t    = threadIdx.x;
    const int warp = t >> 5, lane = t & 31;
    const int tile = blockIdx.x;
    const int kidx = blockIdx.y;

    __half* As = (__half*)(smem_dyn + SM_A);
    const uint32_t qb0 = s2u(smem_dyn + SM_Q0);
    const uint32_t qb1 = s2u(smem_dyn + SM_Q1);

    // --- Kick off chunks 0,1 (per-warp groups) ---
    stage_warp(qw, tile, kidx, 0, qb0, warp, lane);
    stage_warp(qw, tile, kidx, 1, qb1, warp, lane);

    // --- Stage A fp16 [16 m][512 k] (pad 520), whole CTA ---
    #pragma unroll
    for (int i = 0; i < 16; i++) {
        int idx = t + i * THREADS;            // 4096 float2
        int m   = idx >> 8;
        int kp  = idx & 255;
        float2 v = *(const float2*)(A + (size_t)m * K_DIM + kidx * KSEG + 2 * kp);
        *(__half2*)&As[m * AS_H + 2 * kp] = __floats2half2_rn(v.x, v.y);
    }
    __syncthreads();                          // A visible to all (only barrier)

    const int nb   = tile * CTA_COLS + warp * 32;
    const int colq = lane >> 2;               // 0..7
    const int kq   = lane & 3;
    const int xorw = colq << 2;               // LDS swizzle term

    size_t soff[4];
    int rbase[4];
    #pragma unroll
    for (int j = 0; j < 4; j++) {
        soff[j]  = (size_t)(nb + j * 8 + colq) * NGROUPS + kidx * 4;
        rbase[j] = (warp * 32 + j * 8 + colq) * 32;   // warp-private rows only
    }

    float scn[4], zzn[4];
    #pragma unroll
    for (int j = 0; j < 4; j++) { scn[j] = scales[soff[j]]; zzn[j] = zeros[soff[j]]; }

    float c[4][4];
    #pragma unroll
    for (int j = 0; j < 4; j++)
        #pragma unroll
        for (int p = 0; p < 4; p++) c[j][p] = 0.0f;

    uint32_t s2[4], c2[4];
    const uint32_t abase = s2u(As) + ((lane & 15) * AS_H + (lane >> 4) * 8) * 2;

    for (int ch = 0; ch < NCH; ch++) {
        // per-warp wait: chunk ch complete; chunk ch+1 may stay in flight
        if (ch == NCH - 1) cp_wait<0>(); else cp_wait<1>();

        if ((ch & 1) == 0) {                  // new quant group (2 chunks = 128 k)
            #pragma unroll
            for (int j = 0; j < 4; j++) {
                s2[j] = h2bits(__float2half2_rn(scn[j]));
                c2[j] = h2bits(__float2half2_rn(-(16.0f + zzn[j]) * scn[j]));
            }
            int g = ch >> 1;
            if (g < 3) {
                #pragma unroll
                for (int j = 0; j < 4; j++) {
                    scn[j] = scales[soff[j] + g + 1];
                    zzn[j] = zeros [soff[j] + g + 1];
                }
            }
        }

        const uint32_t* qwords =
            (const uint32_t*)(smem_dyn + ((ch & 1) ? SM_Q1 : SM_Q0));
        #pragma unroll
        for (int ls = 0; ls < 4; ls++) {
            const int s = ch * 4 + ls;
            uint32_t a0, a1, a2, a3;
            asm volatile("ldmatrix.sync.aligned.m8n8.x4.shared.b16 {%0,%1,%2,%3}, [%4];"
                         : "=r"(a0), "=r"(a1), "=r"(a2), "=r"(a3)
                         : "r"(abase + s * 32));
            const int w0 = (8 * ls + kq) ^ xorw;
            const int w1 = (8 * ls + 4 + kq) ^ xorw;
            uint32_t q0[4], q1[4];
            #pragma unroll
            for (int j = 0; j < 4; j++) {
                q0[j] = qwords[rbase[j] + w0];
                q1[j] = qwords[rbase[j] + w1];
            }
            #pragma unroll
            for (int j = 0; j < 4; j++) {
                uint32_t b0 = dq(q0[j], s2[j], c2[j]);
                uint32_t b1 = dq(q1[j], s2[j], c2[j]);
                MMA(c[j], a0, a1, a2, a3, b0, b1);
            }
        }

        // refill just-consumed buffer with this warp's OWN rows (no barrier:
        // only this warp reads/writes those rows, and its reads are done)
        if (ch + 2 < NCH)
            stage_warp(qw, tile, kidx, ch + 2, (ch & 1) ? qb1 : qb0, warp, lane);
    }

    // --- Store fp32 partials [kidx][n][m] ---
    #pragma unroll
    for (int j = 0; j < 4; j++) {
        int n0 = nb + j * 8 + 2 * kq;         // D cols = 2*(lane&3), +1
        int m0 = colq;                        // D rows = lane>>2, +8
        float* base = g_scratch + ((size_t)kidx * N_DIM + n0) * M_DIM;
        base[m0]              = c[j][0];
        base[M_DIM + m0]      = c[j][1];
        base[m0 + 8]          = c[j][2];
        base[M_DIM + m0 + 8]  = c[j][3];
    }

    // --- Ticket: last CTA of this tile reduces (deterministic k order) ---
    __threadfence();
    __syncthreads();
    if (t == 0) s_ticket = atomicAdd(&g_cnt[tile], 1);
    __syncthreads();
    if (s_ticket == KSPLIT - 1) {
        if (t == 0) g_cnt[tile] = 0;          // reset for next graph replay
        __threadfence();                       // acquire all partials
        int n = tile * CTA_COLS + t;
        float4 a0 = make_float4(0.f, 0.f, 0.f, 0.f), a1 = a0, a2 = a0, a3 = a0;
        #pragma unroll
        for (int kk = 0; kk < KSPLIT; kk++) {
            const float4* p = (const float4*)(g_scratch + ((size_t)kk * N_DIM + n) * M_DIM);
            float4 v0 = p[0], v1 = p[1], v2 = p[2], v3 = p[3];
            a0.x += v0.x; a0.y += v0.y; a0.z += v0.z; a0.w += v0.w;
            a1.x += v1.x; a1.y += v1.y; a1.z += v1.z; a1.w += v1.w;
            a2.x += v2.x; a2.y += v2.y; a2.z += v2.z; a2.w += v2.w;
            a3.x += v3.x; a3.y += v3.y; a3.z += v3.z; a3.w += v3.w;
        }
        float bv = bias[n];
        float r[16] = {a0.x, a0.y, a0.z, a0.w, a1.x, a1.y, a1.z, a1.w,
                       a2.x, a2.y, a2.z, a2.w, a3.x, a3.y, a3.z, a3.w};
        #pragma unroll
        for (int m = 0; m < 16; m++)
            out[(size_t)m * N_DIM + n] = r[m] + bv;
    }
}

extern "C" void kernel_launch(void* const* d_in, const int* in_sizes, int n_in,
                              void* d_out, int out_size) {
    const float* A      = (const float*)d_in[0];
    const int*   qwv    = (const int*)  d_in[1];
    const float* scales = (const float*)d_in[2];
    const float* zeros  = (const float*)d_in[3];
    const float* bias   = (const float*)d_in[4];
    float* out = (float*)d_out;

    cudaFuncSetAttribute(gptq_hmma, cudaFuncAttributeMaxDynamicSharedMemorySize, SM_TOT);
    gptq_hmma<<<dim3(NT, KSPLIT), THREADS, SM_TOT>>>(A, qwv, scales, zeros, bias, out);
}